// round 12
// baseline (speedup 1.0000x reference)
#include <cuda_runtime.h>
#include <cstdint>

#define KNB   32
#define KP    15
#define CIN   64
#define COUT  128
#define KTOT  (KP * CIN)     // 960
#define NMAX  65536
#define INV_SIGMA 10.0f

typedef unsigned long long u64;
typedef unsigned int u32;

__device__ float g_weighted[(size_t)NMAX * KTOT];   // 240MB scratch (tf32-rounded)
__device__ float g_Wt[COUT * KTOT];                 // W transposed [n][k], tf32-rounded

__device__ __forceinline__ u32 tf32r(float x) {
    u32 r;
    asm("cvt.rna.tf32.f32 %0, %1;" : "=r"(r) : "f"(x));
    return r;
}
__device__ __forceinline__ float fsqrt_approx(float x) {
    float r;
    asm("sqrt.approx.f32 %0, %1;" : "=f"(r) : "f"(x));
    return r;
}
__device__ __forceinline__ void mma_tf32(float* c, u32 a0, u32 a1, u32 a2, u32 a3,
                                         u32 b0, u32 b1) {
    asm("mma.sync.aligned.m16n8k8.row.col.f32.tf32.tf32.f32 "
        "{%0,%1,%2,%3}, {%4,%5,%6,%7}, {%8,%9}, {%0,%1,%2,%3};"
        : "+f"(c[0]), "+f"(c[1]), "+f"(c[2]), "+f"(c[3])
        : "r"(a0), "r"(a1), "r"(a2), "r"(a3), "r"(b0), "r"(b1));
}

// ------------------------------------------------------------ W transpose (+tf32 round)
__global__ void wt_kernel(const float* __restrict__ W) {
    int i = blockIdx.x * 256 + threadIdx.x;     // over KTOT*COUT
    if (i < KTOT * COUT) {
        int k = i >> 7;          // KTOT index
        int n = i & 127;         // COUT index
        ((u32*)g_Wt)[n * KTOT + k] = tf32r(W[i]);
    }
}

// ---------------------------------------------------------------- stage 1+2 (MMA)
// One warp per point. weighted[16][64] = infl[16][32] @ F[32][64] via
// 4 k-chunks x 8 n8-tiles of mma m16n8k8 tf32.
//   sI [16][36]: infl, row 15 zeroed. a-frag bank = (4r+q) bijective, conflict-free.
//   sF [32][72]: gathered feats.      b-frag bank = (8q+r) bijective, conflict-free.
// NOTE: sF/sI are __align__(16): sF is written through float4* (R10 faulted
// on misaligned address because plain __shared__ float is only 4B-aligned).
#define S2W 4   // points (warps) per block
#define SIW 36  // sI row stride (floats)
#define SFW 72  // sF row stride (floats)

__global__ void __launch_bounds__(128)
stage12_mma(const float* __restrict__ pos,
            const float* __restrict__ feats,
            const float* __restrict__ kpts,
            const void*  __restrict__ nbrs,
            int N)
{
    __shared__ __align__(16) float sF[S2W][KNB * SFW];
    __shared__ __align__(16) float sI[S2W][16 * SIW];
    __shared__ float sKP[KP * 3];
    __shared__ int   sNbr[S2W][KNB];
    __shared__ int   sIs64;

    const int tid  = threadIdx.x;
    const int w    = tid >> 5;
    const int lane = tid & 31;

    if (tid < KP * 3) sKP[tid] = kpts[tid];
    if (tid == 0) {
        // indices < 2^16: int64 little-endian => odd 32-bit words are 0
        const int* q = (const int*)nbrs;
        int zeros = 0;
#pragma unroll
        for (int i = 0; i < 32; i++) zeros += (q[2 * i + 1] == 0) ? 1 : 0;
        sIs64 = (zeros >= 30) ? 1 : 0;
    }
    __syncthreads();

    const int n = blockIdx.x * S2W + w;
    if (n >= N) return;                 // whole-warp uniform

    // ---- geometry: lane = neighbor j
    int nbi;
    if (sIs64) nbi = (int)((const long long*)nbrs)[(long long)n * KNB + lane];
    else       nbi = ((const int*)nbrs)[n * KNB + lane];
    sNbr[w][lane] = nbi;

    const float rx = pos[3 * nbi + 0] - pos[3 * n + 0];
    const float ry = pos[3 * nbi + 1] - pos[3 * n + 1];
    const float rz = pos[3 * nbi + 2] - pos[3 * n + 2];
#pragma unroll
    for (int kp = 0; kp < KP; kp++) {
        const float dx = rx - sKP[3 * kp + 0];
        const float dy = ry - sKP[3 * kp + 1];
        const float dz = rz - sKP[3 * kp + 2];
        const float d2 = dx * dx + dy * dy + dz * dz;
        const float v  = fmaxf(0.0f, 1.0f - fsqrt_approx(d2) * INV_SIGMA);
        sI[w][kp * SIW + lane] = v;
    }
    sI[w][15 * SIW + lane] = 0.0f;      // pad row (kp=15)

    // ---- gather F[j][c] -> smem (32 rows x 64 floats, stride 72)
#pragma unroll
    for (int it = 0; it < 16; it++) {
        const int t   = it * 32 + lane;
        const int row = t >> 4;
        const int seg = t & 15;
        const float4 fv = *(const float4*)(feats + (size_t)sNbr[w][row] * CIN + seg * 4);
        *(float4*)(&sF[w][row * SFW + seg * 4]) = fv;
    }
    __syncwarp();

    // ---- MMA: weighted = infl @ F
    const int q = lane & 3;
    const int r = lane >> 2;

    float acc[8][4];
#pragma unroll
    for (int n8 = 0; n8 < 8; n8++)
#pragma unroll
        for (int i = 0; i < 4; i++) acc[n8][i] = 0.0f;

#pragma unroll
    for (int kc = 0; kc < 4; kc++) {
        const int k0 = kc * 8;
        const u32 a0 = __float_as_uint(sI[w][r * SIW + k0 + q]);
        const u32 a1 = __float_as_uint(sI[w][(r + 8) * SIW + k0 + q]);
        const u32 a2 = __float_as_uint(sI[w][r * SIW + k0 + q + 4]);
        const u32 a3 = __float_as_uint(sI[w][(r + 8) * SIW + k0 + q + 4]);
#pragma unroll
        for (int n8 = 0; n8 < 8; n8++) {
            const u32 b0 = __float_as_uint(sF[w][(k0 + q) * SFW + n8 * 8 + r]);
            const u32 b1 = __float_as_uint(sF[w][(k0 + q + 4) * SFW + n8 * 8 + r]);
            mma_tf32(acc[n8], a0, a1, a2, a3, b0, b1);
        }
    }

    // ---- store tf32-rounded weighted[kp][c] (skip pad row kp=15)
    u32* gp = (u32*)(g_weighted + (size_t)n * KTOT);
#pragma unroll
    for (int n8 = 0; n8 < 8; n8++) {
        const int col = n8 * 8 + 2 * q;
        u64 pk0 = ((u64)tf32r(acc[n8][1]) << 32) | tf32r(acc[n8][0]);
        *(u64*)(gp + r * CIN + col) = pk0;
        if (r < 7) {
            u64 pk1 = ((u64)tf32r(acc[n8][3]) << 32) | tf32r(acc[n8][2]);
            *(u64*)(gp + (r + 8) * CIN + col) = pk1;
        }
    }
}

// ------------------------------------------------------------------ stage 3
// out[N,128] = g_weighted[N,960] @ g_Wt^T  via mma.sync m16n8k8 tf32.
// CTA 128x128, K chunks of 32 (4 k8-steps), double-buffered smem.
// Smem per k8-step plane: [128 rows][8 k-interleaved], pos = 2*(k&3)+(k>>2),
// so fragment cols {c, c+4} are adjacent -> one lds.64 per fragment pair.
#define NC 30

__global__ void __launch_bounds__(256)
stage3_hmma(float* __restrict__ out, int N)
{
    extern __shared__ float sm[];   // As [2][4][128][8] @0 ; Bs same @8192
    const int tid  = threadIdx.x;
    const int w    = tid >> 5;
    const int lane = tid & 31;
    const int wm   = (w & 1) * 64;
    const int wn   = (w >> 1) * 32;
    const int m0   = blockIdx.x * 128;

    // global load mapping: thread -> row = tid>>1, 16 floats at hf
    const int row = tid >> 1;
    const int hf  = (tid & 1) * 16;
    const float* Ab = g_weighted + (size_t)(m0 + row) * KTOT + hf;
    const float* Bb = g_Wt + (size_t)row * KTOT + hf;

    float acc[4][4][4];
#pragma unroll
    for (int mt = 0; mt < 4; mt++)
#pragma unroll
        for (int nt = 0; nt < 4; nt++)
#pragma unroll
            for (int q = 0; q < 4; q++) acc[mt][nt][q] = 0.0f;

    float4 ar[4], br[4];

    // prefetch + stage chunk 0
#pragma unroll
    for (int i = 0; i < 4; i++) {
        ar[i] = *(const float4*)(Ab + i * 4);
        br[i] = *(const float4*)(Bb + i * 4);
    }
#pragma unroll
    for (int i = 0; i < 4; i++) {
        const int k0 = hf + i * 4;
        const int s  = k0 >> 3;
        const int bp = (k0 >> 2) & 1;
        float* Ad = sm + s * 1024 + row * 8 + bp;
        float* Bd = sm + 8192 + s * 1024 + row * 8 + bp;
        Ad[0] = ar[i].x; Ad[2] = ar[i].y; Ad[4] = ar[i].z; Ad[6] = ar[i].w;
        Bd[0] = br[i].x; Bd[2] = br[i].y; Bd[4] = br[i].z; Bd[6] = br[i].w;
    }
    __syncthreads();

    for (int c = 0; c < NC; c++) {
        const int cur = c & 1;
        if (c + 1 < NC) {
            const int ko = (c + 1) * 32;
#pragma unroll
            for (int i = 0; i < 4; i++) {
                ar[i] = *(const float4*)(Ab + ko + i * 4);
                br[i] = *(const float4*)(Bb + ko + i * 4);
            }
        }

        // compute on buffer cur: 4 k8-steps
#pragma unroll
        for (int s = 0; s < 4; s++) {
            const float* Abase = sm + cur * 4096 + s * 1024;
            const float* Bbase = sm + 8192 + cur * 4096 + s * 1024;
            u32 a[4][4];
#pragma unroll
            for (int mt = 0; mt < 4; mt++) {
                const int r0 = wm + mt * 16 + (lane >> 2);
                const uint2 lo = *(const uint2*)(Abase + r0 * 8 + 2 * (lane & 3));
                const uint2 hi = *(const uint2*)(Abase + (r0 + 8) * 8 + 2 * (lane & 3));
                a[mt][0] = lo.x; a[mt][1] = hi.x; a[mt][2] = lo.y; a[mt][3] = hi.y;
            }
#pragma unroll
            for (int nt = 0; nt < 4; nt++) {
                const int n = wn + nt * 8 + (lane >> 2);
                const uint2 bb = *(const uint2*)(Bbase + n * 8 + 2 * (lane & 3));
#pragma unroll
                for (int mt = 0; mt < 4; mt++)
                    mma_tf32(acc[mt][nt], a[mt][0], a[mt][1], a[mt][2], a[mt][3],
                             bb.x, bb.y);
            }
        }

        if (c + 1 < NC) {
            const int nxt = cur ^ 1;
#pragma unroll
            for (int i = 0; i < 4; i++) {
                const int k0 = hf + i * 4;
                const int s  = k0 >> 3;
                const int bp = (k0 >> 2) & 1;
                float* Ad = sm + nxt * 4096 + s * 1024 + row * 8 + bp;
                float* Bd = sm + 8192 + nxt * 4096 + s * 1024 + row * 8 + bp;
                Ad[0] = ar[i].x; Ad[2] = ar[i].y; Ad[4] = ar[i].z; Ad[6] = ar[i].w;
                Bd[0] = br[i].x; Bd[2] = br[i].y; Bd[4] = br[i].z; Bd[6] = br[i].w;
            }
            __syncthreads();
        }
    }

    // epilogue: c0,c1 -> (row, 2c+{0,1}); c2,c3 -> row+8
#pragma unroll
    for (int mt = 0; mt < 4; mt++) {
        const int r0 = m0 + wm + mt * 16 + (lane >> 2);
#pragma unroll
        for (int nt = 0; nt < 4; nt++) {
            const int n = wn + nt * 8 + 2 * (lane & 3);
            if (r0 < N)
                *(float2*)(out + (size_t)r0 * COUT + n) =
                    make_float2(acc[mt][nt][0], acc[mt][nt][1]);
            if (r0 + 8 < N)
                *(float2*)(out + (size_t)(r0 + 8) * COUT + n) =
                    make_float2(acc[mt][nt][2], acc[mt][nt][3]);
        }
    }
}

extern "C" void kernel_launch(void* const* d_in, const int* in_sizes, int n_in,
                              void* d_out, int out_size)
{
    const float* pos   = (const float*)d_in[0];
    const float* feats = (const float*)d_in[1];
    const float* kpts  = (const float*)d_in[2];
    const float* W     = (const float*)d_in[3];
    const void*  nbrs  = d_in[4];
    float* out = (float*)d_out;

    const int N = in_sizes[1] / CIN;   // feats is [N, CIN]

    const int SMEM = 2 * 4096 * 2 * 4;   // 64KB for stage3
    cudaFuncSetAttribute(stage3_hmma,
                         cudaFuncAttributeMaxDynamicSharedMemorySize, SMEM);

    wt_kernel<<<(KTOT * COUT + 255) / 256, 256>>>(W);

    stage12_mma<<<(N + S2W - 1) / S2W, 128>>>(pos, feats, kpts, nbrs, N);

    stage3_hmma<<<(N + 127) / 128, 256, SMEM>>>(out, N);
}

// round 13
// speedup vs baseline: 1.7615x; 1.7615x over previous
#include <cuda_runtime.h>
#include <cstdint>

#define KNB   32
#define KP    15
#define CIN   64
#define COUT  128
#define KTOT  (KP * CIN)     // 960
#define NMAX  65536
#define INV_SIGMA 10.0f

typedef unsigned long long u64;
typedef unsigned int u32;

__device__ float g_weighted[(size_t)NMAX * KTOT];   // 240MB scratch (tf32-rounded)
__device__ float g_Wt[COUT * KTOT];                 // W transposed [n][k], tf32-rounded

__device__ __forceinline__ void fma2(u64& d, u64 a, u64 b) {
    asm("fma.rn.f32x2 %0, %1, %2, %0;" : "+l"(d) : "l"(a), "l"(b));
}
__device__ __forceinline__ u32 tf32r(float x) {
    u32 r;
    asm("cvt.rna.tf32.f32 %0, %1;" : "=r"(r) : "f"(x));
    return r;
}
__device__ __forceinline__ u32 smem_u32(const void* p) {
    u32 a;
    asm("{ .reg .u64 t; cvta.to.shared.u64 t, %1; cvt.u32.u64 %0, t; }" : "=r"(a) : "l"(p));
    return a;
}
__device__ __forceinline__ void cp16(u32 dst, const void* src) {
    asm volatile("cp.async.cg.shared.global [%0], [%1], 16;" :: "r"(dst), "l"(src));
}
__device__ __forceinline__ void mma_tf32(float* c, u32 a0, u32 a1, u32 a2, u32 a3,
                                         u32 b0, u32 b1) {
    asm("mma.sync.aligned.m16n8k8.row.col.f32.tf32.tf32.f32 "
        "{%0,%1,%2,%3}, {%4,%5,%6,%7}, {%8,%9}, {%0,%1,%2,%3};"
        : "+f"(c[0]), "+f"(c[1]), "+f"(c[2]), "+f"(c[3])
        : "r"(a0), "r"(a1), "r"(a2), "r"(a3), "r"(b0), "r"(b1));
}

// ------------------------------------------------------------ W transpose (+tf32 round)
__global__ void wt_kernel(const float* __restrict__ W) {
    int i = blockIdx.x * 256 + threadIdx.x;     // over KTOT*COUT
    if (i < KTOT * COUT) {
        int k = i >> 7;          // KTOT index
        int n = i & 127;         // COUT index
        ((u32*)g_Wt)[n * KTOT + k] = tf32r(W[i]);
    }
}

// ---------------------------------------------------------------- stage 1+2 (R7 scalar)
// One warp per point; lane j = neighbor for geometry; then lane owns c-pair.
__global__ void __launch_bounds__(256)
stage12_kernel(const float* __restrict__ pos,
               const float* __restrict__ feats,
               const float* __restrict__ kpts,
               const void*  __restrict__ nbrs,
               int N)
{
    __shared__ float  sKP[KP * 3];
    __shared__ int    sNbr[8][KNB];
    __shared__ float2 sInfl[8][KP * KNB];
    __shared__ int    sIs64;

    const int tid  = threadIdx.x;
    const int wid  = tid >> 5;
    const int lane = tid & 31;

    if (tid < KP * 3) sKP[tid] = kpts[tid];
    if (tid == 0) {
        // indices < 2^16: int64 little-endian => odd 32-bit words are 0
        const int* p = (const int*)nbrs;
        int zeros = 0;
#pragma unroll
        for (int i = 0; i < 32; i++) zeros += (p[2 * i + 1] == 0) ? 1 : 0;
        sIs64 = (zeros >= 30) ? 1 : 0;
    }
    __syncthreads();

    const int n = blockIdx.x * 8 + wid;
    if (n >= N) return;

    int nbi;
    if (sIs64) nbi = (int)((const long long*)nbrs)[(long long)n * KNB + lane];
    else       nbi = ((const int*)nbrs)[n * KNB + lane];
    sNbr[wid][lane] = nbi;

    const float cx = pos[3 * n + 0];
    const float cy = pos[3 * n + 1];
    const float cz = pos[3 * n + 2];
    const float rx = pos[3 * nbi + 0] - cx;
    const float ry = pos[3 * nbi + 1] - cy;
    const float rz = pos[3 * nbi + 2] - cz;
#pragma unroll
    for (int kp = 0; kp < KP; kp++) {
        const float dx = rx - sKP[3 * kp + 0];
        const float dy = ry - sKP[3 * kp + 1];
        const float dz = rz - sKP[3 * kp + 2];
        const float dist = sqrtf(dx * dx + dy * dy + dz * dz);
        const float v = fmaxf(0.0f, 1.0f - dist * INV_SIGMA);
        sInfl[wid][kp * KNB + lane] = make_float2(v, v);
    }
    __syncwarp();

    u64 acc[KP];
#pragma unroll
    for (int kp = 0; kp < KP; kp++) acc[kp] = 0ULL;

#pragma unroll 4
    for (int j = 0; j < KNB; j++) {
        const int nb = sNbr[wid][j];
        const u64 f = *(const u64*)(feats + (size_t)nb * CIN + 2 * lane);
#pragma unroll
        for (int kp = 0; kp < KP; kp++) {
            const u64 s = *(const u64*)(&sInfl[wid][kp * KNB + j]);
            fma2(acc[kp], s, f);
        }
    }

    // store tf32-rounded so stage3's HMMA sees RN-rounded tf32 inputs
    u32* gp = (u32*)(g_weighted + (size_t)n * KTOT + 2 * lane);
#pragma unroll
    for (int kp = 0; kp < KP; kp++) {
        const u32 lo = tf32r(__uint_as_float((u32)(acc[kp] & 0xFFFFFFFFULL)));
        const u32 hi = tf32r(__uint_as_float((u32)(acc[kp] >> 32)));
        u64 pk = ((u64)hi << 32) | lo;
        *(u64*)(gp + kp * CIN) = pk;
    }
}

// ------------------------------------------------------------------ stage 3
// out[N,128] = g_weighted[N,960] @ g_Wt^T via mma.sync m16n8k8 tf32.
// CTA 128x128, K in 30 chunks of 32; 3-stage cp.async smem pipeline.
// Tiles row-major with row stride 36 floats: bank(row*36+k) = (4*row+k)%32,
// bijective over the fragment lanes (r<8, q<4) -> all LDS.32 conflict-free.
#define NC    30
#define RSTR  36                 // row stride (floats)
#define TILE_F (128 * RSTR)      // floats per tile
#define STG_F  (2 * TILE_F)      // A + B per stage
#define STG_B  (STG_F * 4)       // 36864 bytes
#define SMEM3  (3 * STG_B)       // 110592 bytes

__global__ void __launch_bounds__(256, 2)
stage3_hmma(float* __restrict__ out, int N)
{
    extern __shared__ float sm[];
    const u32 sbase = smem_u32(sm);
    const int tid  = threadIdx.x;
    const int w    = tid >> 5;
    const int lane = tid & 31;
    const int wm   = (w & 1) * 64;
    const int wn   = (w >> 1) * 32;
    const int m0   = blockIdx.x * 128;
    const int q    = lane & 3;
    const int r    = lane >> 2;

    // cp.async mapping: 4 x 16B for A, 4 x 16B for B per thread per chunk
    // id = tid + i*256 : row = id>>3 (0..127), s4 = id&7 (float4 within 32-k row)
    const float* Ag = g_weighted + (size_t)m0 * KTOT;

    auto issue = [&](int ck, int buf) {
        const u32 ab = sbase + buf * STG_B;
        const u32 bb = ab + TILE_F * 4;
#pragma unroll
        for (int i = 0; i < 4; i++) {
            const int id  = tid + i * 256;
            const int row = id >> 3;
            const int s4  = id & 7;
            cp16(ab + row * (RSTR * 4) + s4 * 16,
                 Ag + (size_t)row * KTOT + ck * 32 + s4 * 4);
            cp16(bb + row * (RSTR * 4) + s4 * 16,
                 g_Wt + (size_t)row * KTOT + ck * 32 + s4 * 4);
        }
    };

    float acc[4][4][4];
#pragma unroll
    for (int mt = 0; mt < 4; mt++)
#pragma unroll
        for (int nt = 0; nt < 4; nt++)
#pragma unroll
            for (int p = 0; p < 4; p++) acc[mt][nt][p] = 0.0f;

    issue(0, 0);
    asm volatile("cp.async.commit_group;" ::: "memory");
    issue(1, 1);
    asm volatile("cp.async.commit_group;" ::: "memory");

    for (int c = 0; c < NC; c++) {
        asm volatile("cp.async.wait_group 1;" ::: "memory");
        __syncthreads();

        const float* sA = sm + (c % 3) * STG_F;
        const float* sB = sA + TILE_F;

#pragma unroll
        for (int s = 0; s < 4; s++) {
            const int k0 = s * 8;
            u32 a[4][4];
#pragma unroll
            for (int mt = 0; mt < 4; mt++) {
                const int r0 = wm + mt * 16 + r;
                a[mt][0] = __float_as_uint(sA[r0 * RSTR + k0 + q]);
                a[mt][1] = __float_as_uint(sA[(r0 + 8) * RSTR + k0 + q]);
                a[mt][2] = __float_as_uint(sA[r0 * RSTR + k0 + q + 4]);
                a[mt][3] = __float_as_uint(sA[(r0 + 8) * RSTR + k0 + q + 4]);
            }
#pragma unroll
            for (int nt = 0; nt < 4; nt++) {
                const int n = wn + nt * 8 + r;
                const u32 b0 = __float_as_uint(sB[n * RSTR + k0 + q]);
                const u32 b1 = __float_as_uint(sB[n * RSTR + k0 + q + 4]);
#pragma unroll
                for (int mt = 0; mt < 4; mt++)
                    mma_tf32(acc[mt][nt], a[mt][0], a[mt][1], a[mt][2], a[mt][3],
                             b0, b1);
            }
        }

        if (c + 2 < NC) issue(c + 2, (c + 2) % 3);
        asm volatile("cp.async.commit_group;" ::: "memory");
    }

    // epilogue: c0,c1 -> (row, 2c+{0,1}); c2,c3 -> row+8
#pragma unroll
    for (int mt = 0; mt < 4; mt++) {
        const int r0 = m0 + wm + mt * 16 + r;
#pragma unroll
        for (int nt = 0; nt < 4; nt++) {
            const int n = wn + nt * 8 + 2 * q;
            if (r0 < N)
                *(float2*)(out + (size_t)r0 * COUT + n) =
                    make_float2(acc[mt][nt][0], acc[mt][nt][1]);
            if (r0 + 8 < N)
                *(float2*)(out + (size_t)(r0 + 8) * COUT + n) =
                    make_float2(acc[mt][nt][2], acc[mt][nt][3]);
        }
    }
}

extern "C" void kernel_launch(void* const* d_in, const int* in_sizes, int n_in,
                              void* d_out, int out_size)
{
    const float* pos   = (const float*)d_in[0];
    const float* feats = (const float*)d_in[1];
    const float* kpts  = (const float*)d_in[2];
    const float* W     = (const float*)d_in[3];
    const void*  nbrs  = d_in[4];
    float* out = (float*)d_out;

    const int N = in_sizes[1] / CIN;   // feats is [N, CIN]

    cudaFuncSetAttribute(stage3_hmma,
                         cudaFuncAttributeMaxDynamicSharedMemorySize, SMEM3);

    // order: stage12 first so ncu's fixed launch-skip samples it, then wt, stage3
    stage12_kernel<<<(N + 7) / 8, 256>>>(pos, feats, kpts, nbrs, N);

    wt_kernel<<<(KTOT * COUT + 255) / 256, 256>>>(W);

    stage3_hmma<<<(N + 127) / 128, 256, SMEM3>>>(out, N);
}